// round 15
// baseline (speedup 1.0000x reference)
#include <cuda_runtime.h>
#include <cstdint>

#define BATCH   256
#define NMAXN   512
#define HDIM    256
#define CDIM    64
#define HIDN    512
#define NEGV   (-1000000000.0f)

// ---------------- device scratch (no allocations allowed) ----------------
__device__ float g_base1[BATCH * HIDN];
__device__ float g_scores[BATCH * NMAXN];
__device__ float g_sw1[2][HIDN];
__device__ float g_sw2[HIDN];
__device__ __align__(16) char g_W1q1[2][HIDN][HDIM];   // [side][n][k] int8 main
__device__ __align__(16) char g_W1q2[2][HIDN][HDIM];   // residual (scale/128)
__device__ __align__(16) char g_W2q1[HIDN][HIDN];
__device__ __align__(16) char g_W2q2[HIDN][HIDN];

// ---------------- smem layout (from 1024-aligned base) -------------------
// [0, 32K)       A s8 (q1 2 planes @0, q2 2 planes @16K); reused as h1 q1 (4 planes) in layer 2
// [32K, 160K)    h1 fp32 staging (first 64K doubles as A fp32 staging early)
// [160K, 192K)   h1 q2 (4 planes)
// [192K, 200K)   W slice buffer (q1 4K @ +0, q2 4K @ +4096)
#define OFF_AQ2   16384u
#define OFF_STG   32768u
#define OFF_H1Q2  163840u
#define OFF_WB    196608u
#define DYN_SMEM  (204800 + 1024)

#define SWZ(o)   ((o) ^ (((o) >> 3) & 0x70))

// ---------------- helpers ----------------
__device__ __forceinline__ uint32_t smem_u32(const void* p) {
    uint32_t a;
    asm("{ .reg .u64 t; cvta.to.shared.u64 t, %1; cvt.u32.u64 %0, t; }" : "=r"(a) : "l"(p));
    return a;
}
__device__ __forceinline__ void sts128(uint32_t a, uint4 v) {
    asm volatile("st.shared.v4.b32 [%0], {%1,%2,%3,%4};"
                 :: "r"(a), "r"(v.x), "r"(v.y), "r"(v.z), "r"(v.w) : "memory");
}
__device__ __forceinline__ void ldsm4(uint32_t* r, uint32_t addr) {
    asm volatile("ldmatrix.sync.aligned.m8n8.x4.shared.b16 {%0,%1,%2,%3}, [%4];"
                 : "=r"(r[0]), "=r"(r[1]), "=r"(r[2]), "=r"(r[3]) : "r"(addr));
}
// s8 k32 mma: fragment byte layout identical to bf16 k16 -> ldmatrix.b16 works
__device__ __forceinline__ void mma_s8(int* c, const uint32_t* a, const uint32_t* b) {
    asm volatile("mma.sync.aligned.m16n8k32.row.col.s32.s8.s8.s32 "
                 "{%0,%1,%2,%3}, {%4,%5,%6,%7}, {%8,%9}, {%0,%1,%2,%3};"
                 : "+r"(c[0]), "+r"(c[1]), "+r"(c[2]), "+r"(c[3])
                 : "r"(a[0]), "r"(a[1]), "r"(a[2]), "r"(a[3]), "r"(b[0]), "r"(b[1]));
}
// quantize 16 floats (4x float4) into 16 main bytes + 16 residual bytes
__device__ __forceinline__ void quant16(const float4* v4, float inv,
                                        uint32_t* wq1, uint32_t* wq2) {
#pragma unroll
    for (int e = 0; e < 4; e++) {
        float4 v = v4[e];
        float t0 = v.x * inv, t1 = v.y * inv, t2 = v.z * inv, t3 = v.w * inv;
        int i0 = __float2int_rn(t0), i1 = __float2int_rn(t1);
        int i2 = __float2int_rn(t2), i3 = __float2int_rn(t3);
        int j0 = __float2int_rn((t0 - i0) * 128.f), j1 = __float2int_rn((t1 - i1) * 128.f);
        int j2 = __float2int_rn((t2 - i2) * 128.f), j3 = __float2int_rn((t3 - i3) * 128.f);
        wq1[e] = (i0 & 255) | ((i1 & 255) << 8) | ((i2 & 255) << 16) | ((i3 & 255) << 24);
        wq2[e] = (j0 & 255) | ((j1 & 255) << 8) | ((j2 & 255) << 16) | ((j3 & 255) << 24);
    }
}

// ============================================================================
// W per-column scales.  grid (4,3), block 128.  z=0,1: W1 side z; z=2: W2
// ============================================================================
__global__ void __launch_bounds__(128) wscale_kernel(
    const float* __restrict__ W1, const float* __restrict__ W2)
{
    int z = blockIdx.y;
    int n = blockIdx.x * 128 + threadIdx.x;
    int K = (z < 2) ? HDIM : HIDN;
    const float* in = (z < 2) ? (W1 + (size_t)z * HDIM * HIDN) : W2;
    float m = 0.f;
    for (int k = 0; k < K; k++) m = fmaxf(m, fabsf(in[(size_t)k * HIDN + n]));
    float s = fmaxf(m, 1e-20f) * (1.f / 127.f);
    if (z < 2) g_sw1[z][n] = s; else g_sw2[n] = s;
}

// ============================================================================
// W pack: transpose + int8 main/residual quantize into [n][k] scratch
// grid (16,16,3), block (32,8)
// ============================================================================
__global__ void __launch_bounds__(256) wpack_kernel(
    const float* __restrict__ W1, const float* __restrict__ W2)
{
    __shared__ float t[32][33];
    int z = blockIdx.z;
    int K = (z < 2) ? HDIM : HIDN;
    int kt = blockIdx.x * 32, nt = blockIdx.y * 32;
    if (kt >= K) return;
    const float* in = (z < 2) ? (W1 + (size_t)z * HDIM * HIDN) : W2;
    char* o1 = (z < 2) ? &g_W1q1[z][0][0] : &g_W2q1[0][0];
    char* o2 = (z < 2) ? &g_W1q2[z][0][0] : &g_W2q2[0][0];
    int tx = threadIdx.x, ty = threadIdx.y;
#pragma unroll
    for (int i = 0; i < 4; i++)
        t[ty + 8 * i][tx] = in[(size_t)(kt + ty + 8 * i) * HIDN + nt + tx];
    __syncthreads();
#pragma unroll
    for (int i = 0; i < 4; i++) {
        int n = nt + ty + 8 * i, k = kt + tx;
        float s = (z < 2) ? g_sw1[z][n] : g_sw2[n];
        float tt = t[tx][ty + 8 * i] / s;
        int q1 = __float2int_rn(tt);
        int q2 = __float2int_rn((tt - q1) * 128.f);
        o1[(size_t)n * K + k] = (char)q1;
        o2[(size_t)n * K + k] = (char)q2;
    }
}

// ============================================================================
// per-batch constant layer-1 contribution (exact fp32)
// ============================================================================
__global__ void __launch_bounds__(HIDN) base_kernel(
    const float* __restrict__ nodes, const float* __restrict__ cc,
    const float* __restrict__ W1, const float* __restrict__ b1,
    const int* __restrict__ dirns, const int* __restrict__ ncnt)
{
    int b = blockIdx.x, tid = threadIdx.x;
    __shared__ float s_src[HDIM];
    __shared__ float s_cc[CDIM];
    int si = ncnt[b] - 1;
    if (tid < HDIM) s_src[tid] = nodes[((size_t)b * NMAXN + si) * HDIM + tid];
    if (tid < CDIM) s_cc[tid]  = cc[(size_t)b * CDIM + tid];
    __syncthreads();
    int coff = (dirns[b] == 1) ? HDIM : 0;
    float acc = b1[tid];
    const float* Wc = W1 + (size_t)coff * HIDN + tid;
#pragma unroll 8
    for (int k = 0; k < HDIM; k++) acc += s_src[k] * Wc[(size_t)k * HIDN];
    const float* Wcc = W1 + (size_t)(2 * HDIM) * HIDN + tid;
#pragma unroll 8
    for (int k = 0; k < CDIM; k++) acc += s_cc[k] * Wcc[(size_t)k * HIDN];
    g_base1[(size_t)b * HIDN + tid] = acc;
}

// ============================================================================
// main fused MLP: compensated int8 mma.  grid (8,256), 256 threads, 1 CTA/SM
// ============================================================================
__global__ void __launch_bounds__(256, 1) mlp_kernel(
    const float* __restrict__ nodes,
    const float* __restrict__ b2g, const float* __restrict__ W3,
    const float* __restrict__ b3,
    const int* __restrict__ dirns, const int* __restrict__ ncnt)
{
    extern __shared__ char dynsm[];
    char* smp = dynsm + ((1024 - ((uintptr_t)dynsm & 1023)) & 1023);
    uint32_t sbase = smem_u32(smp);

    __shared__ float s_base[128], s_ws[128], s_b2[128], s_w3[128];
    __shared__ float s_sa[64], s_sh[64], s_score[64];

    int b    = blockIdx.y;
    int d0   = blockIdx.x * 64;
    int tid  = threadIdx.x;
    int lane = tid & 31;
    int w    = tid >> 5;
    int wm   = w >> 2;
    int wn   = w & 3;

    int lim = ncnt[b] - 1;
    if (d0 >= lim) {                      // fully-invalid tile: early exit
        if (tid < 64) g_scores[(size_t)b * NMAXN + d0 + tid] = NEGV;
        return;
    }

    if (tid < 64) s_score[tid] = 0.0f;
    int vs = (dirns[b] == 1) ? 0 : 1;

    // ---- stage A fp32 (64x256) into staging region ----
    {
        const float4* Ag4 = (const float4*)(nodes + ((size_t)b * NMAXN + d0) * HDIM);
        float4* st4 = (float4*)(smp + OFF_STG);
#pragma unroll
        for (int i = 0; i < 16; i++) st4[tid + i * 256] = Ag4[tid + i * 256];
    }
    __syncthreads();

    // ---- per-row scale + quantize A -> s8 planes ----
    {
        int row = tid >> 2, q = tid & 3;
        const float4* rp = (const float4*)((const float*)(smp + OFF_STG) + row * HDIM + q * 64);
        float m = 0.f;
#pragma unroll
        for (int j = 0; j < 16; j++) {
            float4 v = rp[j];
            m = fmaxf(m, fmaxf(fmaxf(fabsf(v.x), fabsf(v.y)), fmaxf(fabsf(v.z), fabsf(v.w))));
        }
        m = fmaxf(m, __shfl_xor_sync(0xffffffffu, m, 1));
        m = fmaxf(m, __shfl_xor_sync(0xffffffffu, m, 2));
        m = fmaxf(m, 1e-20f);
        s_sa[row] = m * (1.f / 127.f);
        float inv = 127.f / m;
#pragma unroll
        for (int j = 0; j < 4; j++) {        // 16 cols each
            uint32_t wq1[4], wq2[4];
            quant16(rp + j * 4, inv, wq1, wq2);
            uint32_t lpa = (uint32_t)(q * 32 + j * 8);       // pair index 0..127
            uint32_t adr = (lpa >> 6) * 8192u + SWZ((uint32_t)row * 128u + (lpa & 63) * 2u);
            sts128(sbase + adr, make_uint4(wq1[0], wq1[1], wq1[2], wq1[3]));
            sts128(sbase + OFF_AQ2 + adr, make_uint4(wq2[0], wq2[1], wq2[2], wq2[3]));
        }
    }

    int accM[2][4][4], accC[2][4][4];
#pragma unroll
    for (int mt = 0; mt < 2; mt++)
#pragma unroll
        for (int nt = 0; nt < 4; nt++)
#pragma unroll
            for (int qq = 0; qq < 4; qq++) { accM[mt][nt][qq] = 0; accC[mt][nt][qq] = 0; }

    // W unit prefetch state: unit t: t<32 layer1 (nc=t>>3, ks=t&7); else layer2
    uint4 Rq1, Rq2;
    {
        const char* p1 = &g_W1q1[vs][0][0];
        const char* p2 = &g_W1q2[vs][0][0];
        int n = tid >> 1, c = tid & 1;
        Rq1 = *(const uint4*)(p1 + (size_t)n * HDIM + c * 16);
        Rq2 = *(const uint4*)(p2 + (size_t)n * HDIM + c * 16);
    }
    __syncthreads();   // A s8 planes visible before first ldsm

    for (int t = 0; t < 96; t++) {
        __syncthreads();                          // W buffer free
        {
            uint32_t o = OFF_WB + (uint32_t)(tid >> 1) * 32u + (uint32_t)(tid & 1) * 16u;
            sts128(sbase + o, Rq1);
            sts128(sbase + o + 4096u, Rq2);
        }
        if (t < 32) {
            if ((t & 7) == 0 && tid < 128) {
                int c = t >> 3;
                s_base[tid] = g_base1[(size_t)b * HIDN + c * 128 + tid];
                s_ws[tid]   = g_sw1[vs][c * 128 + tid];
            }
        } else {
            int u = t - 32;
            if ((u & 15) == 0 && tid < 128) {
                int nc = u >> 4;
                s_b2[tid] = b2g[nc * 128 + tid];
                s_w3[tid] = W3[nc * 128 + tid];
                s_ws[tid] = g_sw2[nc * 128 + tid];
            }
        }
        __syncthreads();                          // W slice + constants visible

        if (t + 1 < 96) {                         // prefetch next unit
            int tn = t + 1;
            const char *p1, *p2; int pitch;
            if (tn < 32) {
                int nc = tn >> 3, ks = tn & 7;
                p1 = &g_W1q1[vs][nc * 128][ks * 32];
                p2 = &g_W1q2[vs][nc * 128][ks * 32];
                pitch = HDIM;
            } else {
                int u = tn - 32, nc = u >> 4, ks = u & 15;
                p1 = &g_W2q1[nc * 128][ks * 32];
                p2 = &g_W2q2[nc * 128][ks * 32];
                pitch = HIDN;
            }
            int n = tid >> 1, c = tid & 1;
            Rq1 = *(const uint4*)(p1 + (size_t)n * pitch + c * 16);
            Rq2 = *(const uint4*)(p2 + (size_t)n * pitch + c * 16);
        }

        // ---- one k32 step ----
        uint32_t q2base = (t < 32) ? OFF_AQ2 : OFF_H1Q2;   // q1 region is at offset 0 both phases
        int kg0 = (t < 32) ? (t & 7) * 16 : ((t - 32) & 15) * 16;   // pair units
        int kk  = kg0 + ((lane >> 4) << 3);
        uint32_t A1[2][4], A2[2][4];
#pragma unroll
        for (int mt = 0; mt < 2; mt++) {
            uint32_t row = (uint32_t)(wm * 32 + mt * 16 + (lane & 15));
            uint32_t ao = (uint32_t)(kk >> 6) * 8192u + SWZ(row * 128u + (uint32_t)(kk & 63) * 2u);
            ldsm4(A1[mt], sbase + ao);
            ldsm4(A2[mt], sbase + q2base + ao);
        }
        uint32_t B1[4][2], B2[4][2];
#pragma unroll
        for (int np = 0; np < 2; np++) {
            uint32_t nl = (uint32_t)(wn * 32 + np * 16 + (lane & 7) + ((lane >> 4) << 3));
            uint32_t bo = OFF_WB + nl * 32u + (uint32_t)((lane >> 3) & 1) * 16u;
            uint32_t r[4];
            ldsm4(r, sbase + bo);
            B1[np * 2][0] = r[0]; B1[np * 2][1] = r[1];
            B1[np * 2 + 1][0] = r[2]; B1[np * 2 + 1][1] = r[3];
            ldsm4(r, sbase + bo + 4096u);
            B2[np * 2][0] = r[0]; B2[np * 2][1] = r[1];
            B2[np * 2 + 1][0] = r[2]; B2[np * 2 + 1][1] = r[3];
        }
#pragma unroll
        for (int mt = 0; mt < 2; mt++)
#pragma unroll
            for (int nt = 0; nt < 4; nt++) {
                mma_s8(accM[mt][nt], A1[mt], B1[nt]);
                mma_s8(accC[mt][nt], A1[mt], B2[nt]);
                mma_s8(accC[mt][nt], A2[mt], B1[nt]);
            }

        // ---- epilogues ----
        bool ep1 = (t < 32) && ((t & 7) == 7);
        bool ep2 = (t >= 32) && (((t - 32) & 15) == 15);
        if (ep1) {
            int nc = t >> 3;
            float* stg = (float*)(smp + OFF_STG);
#pragma unroll
            for (int mt = 0; mt < 2; mt++)
#pragma unroll
                for (int nt = 0; nt < 4; nt++)
#pragma unroll
                    for (int rh = 0; rh < 2; rh++) {
                        int row = wm * 32 + mt * 16 + (lane >> 2) + rh * 8;
                        int nl  = wn * 32 + nt * 8 + 2 * (lane & 3);
                        float fa = s_sa[row];
                        float v0 = fa * s_ws[nl] *
                                   ((float)accM[mt][nt][rh * 2] + (float)accC[mt][nt][rh * 2] * 0.0078125f)
                                   + s_base[nl];
                        float v1 = fa * s_ws[nl + 1] *
                                   ((float)accM[mt][nt][rh * 2 + 1] + (float)accC[mt][nt][rh * 2 + 1] * 0.0078125f)
                                   + s_base[nl + 1];
                        float2 hv = make_float2(fmaxf(v0, 0.f), fmaxf(v1, 0.f));
                        *(float2*)&stg[(size_t)row * HIDN + nc * 128 + nl] = hv;
                    }
        }
        if (t == 31) {
            __syncthreads();   // all h1 fp32 staged; all layer-1 ldsm of A done
            int row = tid >> 2, q = tid & 3;
            const float4* rp = (const float4*)((const float*)(smp + OFF_STG) + (size_t)row * HIDN + q * 128);
            float m = 0.f;
#pragma unroll
            for (int j = 0; j < 32; j++) {
                float4 v = rp[j];
                m = fmaxf(m, fmaxf(fmaxf(v.x, v.y), fmaxf(v.z, v.w)));  // h1 >= 0
            }
            m = fmaxf(m, __shfl_xor_sync(0xffffffffu, m, 1));
            m = fmaxf(m, __shfl_xor_sync(0xffffffffu, m, 2));
            m = fmaxf(m, 1e-20f);
            s_sh[row] = m * (1.f / 127.f);
            float inv = 127.f / m;
#pragma unroll
            for (int j = 0; j < 8; j++) {    // 16 cols each -> pairs q*64 + j*8
                uint32_t wq1[4], wq2[4];
                quant16(rp + j * 4, inv, wq1, wq2);
                uint32_t adr = (uint32_t)q * 8192u + SWZ((uint32_t)row * 128u + (uint32_t)j * 16u);
                sts128(sbase + adr, make_uint4(wq1[0], wq1[1], wq1[2], wq1[3]));
                sts128(sbase + OFF_H1Q2 + adr, make_uint4(wq2[0], wq2[1], wq2[2], wq2[3]));
            }
            // next loop iteration's __syncthreads publishes h1 s8 before first layer-2 ldsm
        }
        if (ep2) {
#pragma unroll
            for (int mt = 0; mt < 2; mt++)
#pragma unroll
                for (int rh = 0; rh < 2; rh++) {
                    int row = wm * 32 + mt * 16 + (lane >> 2) + rh * 8;
                    float sh = s_sh[row];
                    float rs = 0.f;
#pragma unroll
                    for (int nt = 0; nt < 4; nt++) {
                        int nl = wn * 32 + nt * 8 + 2 * (lane & 3);
                        float v0 = sh * s_ws[nl] *
                                   ((float)accM[mt][nt][rh * 2] + (float)accC[mt][nt][rh * 2] * 0.0078125f)
                                   + s_b2[nl];
                        float v1 = sh * s_ws[nl + 1] *
                                   ((float)accM[mt][nt][rh * 2 + 1] + (float)accC[mt][nt][rh * 2 + 1] * 0.0078125f)
                                   + s_b2[nl + 1];
                        rs += fmaxf(v0, 0.f) * s_w3[nl] + fmaxf(v1, 0.f) * s_w3[nl + 1];
                    }
                    rs += __shfl_xor_sync(0xffffffffu, rs, 1);
                    rs += __shfl_xor_sync(0xffffffffu, rs, 2);
                    if ((lane & 3) == 0) atomicAdd(&s_score[row], rs);
                }
        }
        if (ep1 || ep2) {
#pragma unroll
            for (int mt = 0; mt < 2; mt++)
#pragma unroll
                for (int nt = 0; nt < 4; nt++)
#pragma unroll
                    for (int qq = 0; qq < 4; qq++) { accM[mt][nt][qq] = 0; accC[mt][nt][qq] = 0; }
        }
    }

    __syncthreads();
    if (tid < 64) {
        int d = d0 + tid;
        g_scores[(size_t)b * NMAXN + d] = (d < lim) ? (s_score[tid] + b3[0]) : NEGV;
    }
}

// ============================================================================
// per-batch log-softmax NLL
// ============================================================================
__global__ void __launch_bounds__(NMAXN) loss_kernel(
    const int* __restrict__ dests, float* __restrict__ out)
{
    int b = blockIdx.x, tid = threadIdx.x;
    __shared__ float red[NMAXN];
    float v = g_scores[(size_t)b * NMAXN + tid];
    red[tid] = v;
    __syncthreads();
    for (int o = 256; o > 0; o >>= 1) {
        if (tid < o) red[tid] = fmaxf(red[tid], red[tid + o]);
        __syncthreads();
    }
    float mx = red[0];
    __syncthreads();
    red[tid] = expf(v - mx);
    __syncthreads();
    for (int o = 256; o > 0; o >>= 1) {
        if (tid < o) red[tid] = red[tid] + red[tid + o];
        __syncthreads();
    }
    if (tid == 0) {
        float sd = g_scores[(size_t)b * NMAXN + dests[b]];
        out[b] = mx + logf(red[0]) - sd;
    }
}

// ============================================================================
extern "C" void kernel_launch(void* const* d_in, const int* in_sizes, int n_in,
                              void* d_out, int out_size)
{
    const float* nodes = (const float*)d_in[0];
    const float* cc    = (const float*)d_in[1];
    const float* W1    = (const float*)d_in[2];
    const float* b1    = (const float*)d_in[3];
    const float* W2    = (const float*)d_in[4];
    const float* b2    = (const float*)d_in[5];
    const float* W3    = (const float*)d_in[6];
    const float* b3    = (const float*)d_in[7];
    const int* dirns   = (const int*)d_in[8];
    const int* ncnt    = (const int*)d_in[9];
    const int* dests   = (const int*)d_in[10];
    float* out = (float*)d_out;

    dim3 sg(4, 3);
    wscale_kernel<<<sg, 128>>>(W1, W2);
    dim3 pg(16, 16, 3), pb(32, 8);
    wpack_kernel<<<pg, pb>>>(W1, W2);

    base_kernel<<<BATCH, HIDN>>>(nodes, cc, W1, b1, dirns, ncnt);

    cudaFuncSetAttribute(mlp_kernel, cudaFuncAttributeMaxDynamicSharedMemorySize, DYN_SMEM);
    dim3 grid(8, BATCH);
    mlp_kernel<<<grid, 256, DYN_SMEM>>>(nodes, b2, W3, b3, dirns, ncnt);

    loss_kernel<<<BATCH, NMAXN>>>(dests, out);
}

// round 16
// speedup vs baseline: 2.1574x; 2.1574x over previous
#include <cuda_runtime.h>
#include <cuda_bf16.h>
#include <cstdint>

#define BATCH   256
#define NMAXN   512
#define HDIM    256
#define CDIM    64
#define HIDN    512
#define NEGV   (-1000000000.0f)

// ---------------- device scratch (no allocations allowed) ----------------
__device__ float g_base1[BATCH * HIDN];
__device__ float g_scores[BATCH * NMAXN];
__device__ __align__(16) __nv_bfloat16 g_W1h[2][HIDN][HDIM];   // [side][n][k]
__device__ __align__(16) __nv_bfloat16 g_W1l[2][HIDN][HDIM];
__device__ __align__(16) __nv_bfloat16 g_W2h[HIDN][HIDN];      // [n][k]
__device__ __align__(16) __nv_bfloat16 g_W2l[HIDN][HIDN];

// ---------------- smem region offsets (from 1024-aligned base) ----------
// A:  64 rows x 256 k bf16, SW128 planes of 64x128B: hi 4*8192, lo +32768
// h1: 64 rows x 512 n bf16: hi 8*8192 @65536, lo @131072
// W slice double buffer: 2 x (128 n x 32 k hi 8192 + lo 8192) @196608
#define OFF_AH   0u
#define OFF_AL   32768u
#define OFF_H1H  65536u
#define OFF_H1L  131072u
#define OFF_WB0  196608u
#define DYN_SMEM (229376 + 1024)

#define SWZ(o)   ((o) ^ (((o) >> 3) & 0x70))
#define SWZ64(o) ((o) ^ (((o) >> 3) & 0x30))

// ---------------- helpers ----------------
__device__ __forceinline__ uint32_t smem_u32(const void* p) {
    uint32_t a;
    asm("{ .reg .u64 t; cvta.to.shared.u64 t, %1; cvt.u32.u64 %0, t; }" : "=r"(a) : "l"(p));
    return a;
}
// pack: x0 -> low 16 bits, x1 -> high 16 bits
__device__ __forceinline__ uint32_t bf2(float x0, float x1) {
    uint32_t r;
    asm("cvt.rn.bf16x2.f32 %0, %1, %2;" : "=r"(r) : "f"(x1), "f"(x0));
    return r;
}
__device__ __forceinline__ float lo_of(uint32_t u) { return __uint_as_float(u << 16); }
__device__ __forceinline__ float hi_of(uint32_t u) { return __uint_as_float(u & 0xffff0000u); }

__device__ __forceinline__ void sts128(uint32_t a, uint4 v) {
    asm volatile("st.shared.v4.b32 [%0], {%1,%2,%3,%4};"
                 :: "r"(a), "r"(v.x), "r"(v.y), "r"(v.z), "r"(v.w) : "memory");
}
__device__ __forceinline__ void sts64v2(uint32_t a, uint32_t x, uint32_t y) {
    asm volatile("st.shared.v2.b32 [%0], {%1,%2};" :: "r"(a), "r"(x), "r"(y) : "memory");
}
__device__ __forceinline__ void sts32(uint32_t a, uint32_t v) {
    asm volatile("st.shared.b32 [%0], %1;" :: "r"(a), "r"(v) : "memory");
}
__device__ __forceinline__ void ldsm4(uint32_t* r, uint32_t addr) {
    asm volatile("ldmatrix.sync.aligned.m8n8.x4.shared.b16 {%0,%1,%2,%3}, [%4];"
                 : "=r"(r[0]), "=r"(r[1]), "=r"(r[2]), "=r"(r[3]) : "r"(addr));
}
__device__ __forceinline__ void mma16816(float* c, const uint32_t* a, const uint32_t* b) {
    asm volatile("mma.sync.aligned.m16n8k16.row.col.f32.bf16.bf16.f32 "
                 "{%0,%1,%2,%3}, {%4,%5,%6,%7}, {%8,%9}, {%0,%1,%2,%3};"
                 : "+f"(c[0]), "+f"(c[1]), "+f"(c[2]), "+f"(c[3])
                 : "r"(a[0]), "r"(a[1]), "r"(a[2]), "r"(a[3]), "r"(b[0]), "r"(b[1]));
}

// unit t (0..95): t<32 -> layer1 (nc=t/8, ks=t%8); else layer2 (nc=(t-32)/16, ks=(t-32)%16)
__device__ __forceinline__ void unit_ptr(int t, int vs,
        const __nv_bfloat16*& hp, const __nv_bfloat16*& lp, int& pitch) {
    if (t < 32) {
        int nc = t >> 3, ks = t & 7;
        hp = &g_W1h[vs][nc * 128][ks * 32];
        lp = &g_W1l[vs][nc * 128][ks * 32];
        pitch = HDIM;
    } else {
        int u = t - 32, nc = u >> 4, ks = u & 15;
        hp = &g_W2h[nc * 128][ks * 32];
        lp = &g_W2l[nc * 128][ks * 32];
        pitch = HIDN;
    }
}
__device__ __forceinline__ void ldg_unit(uint4* R, const __nv_bfloat16* hp,
        const __nv_bfloat16* lp, int pitch, int tid) {
#pragma unroll
    for (int i = 0; i < 2; i++) {
        int idx = tid + i * 256;            // 512 uint4 per hi/lo
        int n = idx >> 2, kq = idx & 3;
        R[i]     = *(const uint4*)(hp + (size_t)n * pitch + kq * 8);
        R[2 + i] = *(const uint4*)(lp + (size_t)n * pitch + kq * 8);
    }
}
__device__ __forceinline__ void sts_unit(uint32_t wbase, const uint4* R, int tid) {
#pragma unroll
    for (int i = 0; i < 2; i++) {
        int idx = tid + i * 256;
        uint32_t n = (uint32_t)(idx >> 2), kq = (uint32_t)(idx & 3);
        uint32_t o = SWZ64(n * 64u + kq * 16u);
        sts128(wbase + o, R[i]);
        sts128(wbase + 8192u + o, R[2 + i]);
    }
}

// ============================================================================
// pack: transpose + hi/lo bf16 split of W1 sides and W2 into [n][k] scratch
// ============================================================================
__global__ void __launch_bounds__(256) pack_kernel(
    const float* __restrict__ W1, const float* __restrict__ W2)
{
    __shared__ float t[32][33];
    int z = blockIdx.z;
    int K = (z < 2) ? HDIM : HIDN;
    int kt = blockIdx.x * 32, nt = blockIdx.y * 32;
    if (kt >= K) return;
    const float* in = (z < 2) ? (W1 + (size_t)z * HDIM * HIDN) : W2;   // [K][512]
    __nv_bfloat16* oh = (z < 2) ? &g_W1h[z][0][0] : &g_W2h[0][0];
    __nv_bfloat16* ol = (z < 2) ? &g_W1l[z][0][0] : &g_W2l[0][0];
    int tx = threadIdx.x, ty = threadIdx.y;
#pragma unroll
    for (int i = 0; i < 4; i++)
        t[ty + 8 * i][tx] = in[(size_t)(kt + ty + 8 * i) * HIDN + nt + tx];
    __syncthreads();
#pragma unroll
    for (int i = 0; i < 4; i++) {
        int n = nt + ty + 8 * i, k = kt + tx;
        float x = t[tx][ty + 8 * i];
        __nv_bfloat16 h = __float2bfloat16(x);
        __nv_bfloat16 l = __float2bfloat16(x - __bfloat162float(h));
        oh[(size_t)n * K + k] = h;
        ol[(size_t)n * K + k] = l;
    }
}

// ============================================================================
// per-batch constant layer-1 contribution (exact fp32)
// ============================================================================
__global__ void __launch_bounds__(HIDN) base_kernel(
    const float* __restrict__ nodes, const float* __restrict__ cc,
    const float* __restrict__ W1, const float* __restrict__ b1,
    const int* __restrict__ dirns, const int* __restrict__ ncnt)
{
    int b = blockIdx.x, tid = threadIdx.x;
    __shared__ float s_src[HDIM];
    __shared__ float s_cc[CDIM];
    int si = ncnt[b] - 1;
    if (tid < HDIM) s_src[tid] = nodes[((size_t)b * NMAXN + si) * HDIM + tid];
    if (tid < CDIM) s_cc[tid]  = cc[(size_t)b * CDIM + tid];
    __syncthreads();
    int coff = (dirns[b] == 1) ? HDIM : 0;
    float acc = b1[tid];
    const float* Wc = W1 + (size_t)coff * HIDN + tid;
#pragma unroll 8
    for (int k = 0; k < HDIM; k++) acc += s_src[k] * Wc[(size_t)k * HIDN];
    const float* Wcc = W1 + (size_t)(2 * HDIM) * HIDN + tid;
#pragma unroll 8
    for (int k = 0; k < CDIM; k++) acc += s_cc[k] * Wcc[(size_t)k * HIDN];
    g_base1[(size_t)b * HIDN + tid] = acc;
}

// ============================================================================
// main fused MLP: mma.sync compensated bf16, double-buffered W, early exit.
// grid (8,256), 256 threads, 1 CTA/SM.
// ============================================================================
__global__ void __launch_bounds__(256, 1) mlp_kernel(
    const float* __restrict__ nodes,
    const float* __restrict__ b2g, const float* __restrict__ W3,
    const float* __restrict__ b3,
    const int* __restrict__ dirns, const int* __restrict__ ncnt)
{
    extern __shared__ char dynsm[];
    uint32_t sbase = (smem_u32(dynsm) + 1023u) & ~1023u;

    __shared__ float s_base[128];
    __shared__ float s_b2[128], s_w3[128];
    __shared__ float s_score[64];

    int b    = blockIdx.y;
    int d0   = blockIdx.x * 64;
    int tid  = threadIdx.x;
    int lane = tid & 31;
    int w    = tid >> 5;
    int wm   = w >> 2;      // 0..1  -> rows [wm*32, +32)
    int wn   = w & 3;       // 0..3  -> cols [wn*32, +32) within 128-chunk

    int lim = ncnt[b] - 1;
    if (d0 >= lim) {        // fully-invalid tile: scores are all NEG, skip compute
        if (tid < 64) g_scores[(size_t)b * NMAXN + d0 + tid] = NEGV;
        return;
    }

    if (tid < 64) s_score[tid] = 0.0f;

    // ---- A tile: 64 rows x 256 k, fp32 -> bf16 hi/lo, SW128 K-major ----
    {
        const float* Ag = nodes + ((size_t)b * NMAXN + d0) * HDIM;
#pragma unroll
        for (int i = 0; i < 16; i++) {
            int g = tid + i * 256;              // 4096 float4
            int row = g >> 6, k4 = (g & 63) * 4;
            float4 v = *(const float4*)(Ag + (size_t)row * HDIM + k4);
            uint32_t h0 = bf2(v.x, v.y), h1 = bf2(v.z, v.w);
            uint32_t l0 = bf2(v.x - lo_of(h0), v.y - hi_of(h0));
            uint32_t l1 = bf2(v.z - lo_of(h1), v.w - hi_of(h1));
            uint32_t off = (uint32_t)(k4 >> 6) * 8192u
                         + SWZ((uint32_t)row * 128u + (uint32_t)(k4 & 63) * 2u);
            sts64v2(sbase + OFF_AH + off, h0, h1);
            sts64v2(sbase + OFF_AL + off, l0, l1);
        }
    }
    int vs = (dirns[b] == 1) ? 0 : 1;

    float acc[2][4][4];
#pragma unroll
    for (int mt = 0; mt < 2; mt++)
#pragma unroll
        for (int nt = 0; nt < 4; nt++)
#pragma unroll
            for (int q = 0; q < 4; q++) acc[mt][nt][q] = 0.0f;

    uint4 R[4];
    // ---- prologue: unit 0 into buffer 0, chunk-0 constants ----
    {
        const __nv_bfloat16 *hp, *lp; int pitch;
        unit_ptr(0, vs, hp, lp, pitch);
        ldg_unit(R, hp, lp, pitch, tid);
        sts_unit(sbase + OFF_WB0, R, tid);
        if (tid < 128) s_base[tid] = g_base1[(size_t)b * HIDN + tid];
    }
    __syncthreads();   // A planes + buf0 + chunk0 constants visible

    for (int t = 0; t < 96; t++) {
        uint32_t wb = sbase + OFF_WB0 + (uint32_t)(t & 1) * 16384u;

        if (t + 1 < 96) {                      // prefetch next unit into regs
            const __nv_bfloat16 *hp, *lp; int pitch;
            unit_ptr(t + 1, vs, hp, lp, pitch);
            ldg_unit(R, hp, lp, pitch, tid);
        }

        // ---- compute: 2 ksteps of 16 within this 32-k slice ----
        uint32_t abase = (t < 32) ? OFF_AH : OFF_H1H;
        uint32_t albas = (t < 32) ? OFF_AL : OFF_H1L;
        int kg0 = (t < 32) ? (t & 7) * 32 : ((t - 32) & 15) * 32;
#pragma unroll
        for (int ks2 = 0; ks2 < 32; ks2 += 16) {
            int kk = kg0 + ks2 + ((lane >> 4) << 3);     // A k coord for this lane
            uint32_t Ah[2][4], Al[2][4];
#pragma unroll
            for (int mt = 0; mt < 2; mt++) {
                uint32_t row = (uint32_t)(wm * 32 + mt * 16 + (lane & 15));
                uint32_t ao = (uint32_t)(kk >> 6) * 8192u
                            + SWZ(row * 128u + (uint32_t)(kk & 63) * 2u);
                ldsm4(Ah[mt], sbase + abase + ao);
                ldsm4(Al[mt], sbase + albas + ao);
            }
            uint32_t Bh[4][2], Bl[4][2];
#pragma unroll
            for (int np = 0; np < 2; np++) {
                uint32_t nl = (uint32_t)(wn * 32 + np * 16 + (lane & 7) + ((lane >> 4) << 3));
                uint32_t kb = (uint32_t)(ks2 + (((lane >> 3) & 1) << 3));
                uint32_t bo = SWZ64(nl * 64u + kb * 2u);
                uint32_t r[4];
                ldsm4(r, wb + bo);
                Bh[np * 2][0] = r[0]; Bh[np * 2][1] = r[1];
                Bh[np * 2 + 1][0] = r[2]; Bh[np * 2 + 1][1] = r[3];
                ldsm4(r, wb + 8192u + bo);
                Bl[np * 2][0] = r[0]; Bl[np * 2][1] = r[1];
                Bl[np * 2 + 1][0] = r[2]; Bl[np * 2 + 1][1] = r[3];
            }
#pragma unroll
            for (int mt = 0; mt < 2; mt++)
#pragma unroll
                for (int nt = 0; nt < 4; nt++) {
                    mma16816(acc[mt][nt], Ah[mt], Bh[nt]);
                    mma16816(acc[mt][nt], Al[mt], Bh[nt]);
                    mma16816(acc[mt][nt], Ah[mt], Bl[nt]);
                }
        }

        // ---- epilogues at chunk boundaries ----
        bool ep1 = (t < 32) && ((t & 7) == 7);
        bool ep2 = (t >= 32) && (((t - 32) & 15) == 15);
        if (ep1) {
            int nc = t >> 3;
#pragma unroll
            for (int mt = 0; mt < 2; mt++)
#pragma unroll
                for (int nt = 0; nt < 4; nt++)
#pragma unroll
                    for (int rh = 0; rh < 2; rh++) {
                        uint32_t row = (uint32_t)(wm * 32 + mt * 16 + (lane >> 2) + rh * 8);
                        int nl = wn * 32 + nt * 8 + 2 * (lane & 3);
                        float f0 = fmaxf(acc[mt][nt][rh * 2]     + s_base[nl],     0.0f);
                        float f1 = fmaxf(acc[mt][nt][rh * 2 + 1] + s_base[nl + 1], 0.0f);
                        uint32_t h = bf2(f0, f1);
                        uint32_t l = bf2(f0 - lo_of(h), f1 - hi_of(h));
                        int ng = nc * 128 + nl;
                        uint32_t off = (uint32_t)(ng >> 6) * 8192u
                                     + SWZ(row * 128u + (uint32_t)(ng & 63) * 2u);
                        sts32(sbase + OFF_H1H + off, h);
                        sts32(sbase + OFF_H1L + off, l);
                    }
        }
        if (ep2) {
#pragma unroll
            for (int mt = 0; mt < 2; mt++)
#pragma unroll
                for (int rh = 0; rh < 2; rh++) {
                    float rs = 0.0f;
#pragma unroll
                    for (int nt = 0; nt < 4; nt++) {
                        int nl = wn * 32 + nt * 8 + 2 * (lane & 3);
                        rs += fmaxf(acc[mt][nt][rh * 2]     + s_b2[nl],     0.0f) * s_w3[nl];
                        rs += fmaxf(acc[mt][nt][rh * 2 + 1] + s_b2[nl + 1], 0.0f) * s_w3[nl + 1];
                    }
                    rs += __shfl_xor_sync(0xffffffffu, rs, 1);
                    rs += __shfl_xor_sync(0xffffffffu, rs, 2);
                    if ((lane & 3) == 0)
                        atomicAdd(&s_score[wm * 32 + mt * 16 + (lane >> 2) + rh * 8], rs);
                }
        }
        if (ep1 || ep2) {
#pragma unroll
            for (int mt = 0; mt < 2; mt++)
#pragma unroll
                for (int nt = 0; nt < 4; nt++)
#pragma unroll
                    for (int q = 0; q < 4; q++) acc[mt][nt][q] = 0.0f;
        }

        // ---- stage next unit into the other buffer + next-chunk constants ----
        if (t + 1 < 96)
            sts_unit(sbase + OFF_WB0 + (uint32_t)((t + 1) & 1) * 16384u, R, tid);
        {
            int tn = t + 1;
            if (tn < 32) {
                if ((tn & 7) == 0 && tid < 128)
                    s_base[tid] = g_base1[(size_t)b * HIDN + (tn >> 3) * 128 + tid];
            } else if (tn < 96) {
                int u = tn - 32;
                if ((u & 15) == 0 && tid < 128) {
                    int nc = u >> 4;
                    s_b2[tid] = b2g[nc * 128 + tid];
                    s_w3[tid] = W3[nc * 128 + tid];
                }
            }
        }
        __syncthreads();   // publishes: next W buffer, constants, h1 (if ep1)
    }

    if (tid < 64) {
        int d = d0 + tid;
        g_scores[(size_t)b * NMAXN + d] = (d < lim) ? (s_score[tid] + b3[0]) : NEGV;
    }
}

// ============================================================================
// per-batch log-softmax NLL
// ============================================================================
__global__ void __launch_bounds__(NMAXN) loss_kernel(
    const int* __restrict__ dests, float* __restrict__ out)
{
    int b = blockIdx.x, tid = threadIdx.x;
    __shared__ float red[NMAXN];
    float v = g_scores[(size_t)b * NMAXN + tid];
    red[tid] = v;
    __syncthreads();
    for (int o = 256; o > 0; o >>= 1) {
        if (tid < o) red[tid] = fmaxf(red[tid], red[tid + o]);
        __syncthreads();
    }
    float mx = red[0];
    __syncthreads();
    red[tid] = expf(v - mx);
    __syncthreads();
    for (int o = 256; o > 0; o >>= 1) {
        if (tid < o) red[tid] = red[tid] + red[tid + o];
        __syncthreads();
    }
    if (tid == 0) {
        float sd = g_scores[(size_t)b * NMAXN + dests[b]];
        out[b] = mx + logf(red[0]) - sd;
    }
}

// ============================================================================
extern "C" void kernel_launch(void* const* d_in, const int* in_sizes, int n_in,
                              void* d_out, int out_size)
{
    const float* nodes = (const float*)d_in[0];
    const float* cc    = (const float*)d_in[1];
    const float* W1    = (const float*)d_in[2];
    const float* b1    = (const float*)d_in[3];
    const float* W2    = (const float*)d_in[4];
    const float* b2    = (const float*)d_in[5];
    const float* W3    = (const float*)d_in[6];
    const float* b3    = (const float*)d_in[7];
    const int* dirns   = (const int*)d_in[8];
    const int* ncnt    = (const int*)d_in[9];
    const int* dests   = (const int*)d_in[10];
    float* out = (float*)d_out;

    dim3 pg(16, 16, 3), pb(32, 8);
    pack_kernel<<<pg, pb>>>(W1, W2);

    base_kernel<<<BATCH, HIDN>>>(nodes, cc, W1, b1, dirns, ncnt);

    cudaFuncSetAttribute(mlp_kernel, cudaFuncAttributeMaxDynamicSharedMemorySize, DYN_SMEM);
    dim3 grid(8, BATCH);
    mlp_kernel<<<grid, 256, DYN_SMEM>>>(nodes, b2, W3, b3, dirns, ncnt);

    loss_kernel<<<BATCH, NMAXN>>>(dests, out);
}